// round 11
// baseline (speedup 1.0000x reference)
#include <cuda_runtime.h>
#include <math.h>
#include <float.h>

// ---------------- problem constants ----------------
#define BB 8
#define SS 128
#define HH 768
#define NS 996
#define HID 150
#define NZ 64
#define NPAIR (NZ*NZ)
#define NSPANS_TOT (BB*NS)      // 7968
#define NPAIRS_TOT (BB*NPAIR)   // 32768
#define NCAT 900
#define BMP 32                  // proj tile rows
#define BMF 64                  // fused-GEMM tile rows (8 per warp)
#define WPITCH 152
#define WROWS 160
#define WSM_FLOATS (WROWS*WPITCH)          // 24320
#define ASM_FLOATS (2*8*8*16)              // 2048
#define DYN_BYTES ((WSM_FLOATS + ASM_FLOATS)*4)   // 105472

#define NTILES_SPAN ((NSPANS_TOT + BMF - 1)/BMF)  // 125
#define NTILES_PAIR (NPAIRS_TOT/BMF)              // 512

// output regions (floats)
#define OUT_SPANS 0
#define OUT_CAND  (BB*NS*3)                 // 23904
#define OUT_TIDX  (OUT_CAND + BB*NPAIR*4)   // 154976
#define OUT_OIDX  (OUT_TIDX + BB*NZ)        // 155488

// ---------------- scratch ----------------
__device__ float g_XH[BB * SS * NCAT];
__device__ float g_WEs[8 * HID];
__device__ float g_WEt[8 * HID];
__device__ float g_WEo[8 * HID];
__device__ float g_Dtab[10 * HID];
__device__ float g_probA[BB * 1024];
__device__ float g_probO[BB * 1024];
__device__ int   g_tS[BB * NZ], g_tE[BB * NZ], g_oS[BB * NZ], g_oE[BB * NZ];
__device__ float g_T[BB * NZ * HID];
__device__ float g_O[BB * NZ * HID];

// ---------------- packed fp32x2 FMA (Blackwell) ----------------
union F2U { float2 f; unsigned long long u; };
static __device__ __forceinline__ float2 ffma2(float2 a, float2 b, float2 c) {
    F2U A, B, C, D; A.f = a; B.f = b; C.f = c;
    asm("fma.rn.f32x2 %0, %1, %2, %3;" : "=l"(D.u) : "l"(A.u), "l"(B.u), "l"(C.u));
    return D.f;
}
static __device__ __forceinline__ float f4c(const float4& v, int k) {
    return k == 0 ? v.x : k == 1 ? v.y : k == 2 ? v.z : v.w;
}

__device__ __forceinline__ void span_decode(int i, int& s, int& e, int& w) {
    int off = 0;
#pragma unroll
    for (int wi = 1; wi <= 8; ++wi) {
        int cnt = SS - wi + 1;
        if (i < off + cnt) { s = i - off; e = s + wi - 1; w = wi - 1; return; }
        off += cnt;
    }
    s = 0; e = 0; w = 0;
}

// ---------------- tiny tables ----------------
__global__ void tables_kernel(const float* __restrict__ width_emb,
                              const float* __restrict__ sW1, const float* __restrict__ sb1,
                              const float* __restrict__ dist_emb,
                              const float* __restrict__ pW1, const float* __restrict__ pb1) {
    int idx = blockIdx.x * 256 + threadIdx.x;
    if (idx < 1200) {
        int r = idx / HID, n = idx % HID;
        float acc = sb1[n];
        for (int k = 0; k < 20; ++k) acc += width_emb[r * 20 + k] * sW1[(1536 + k) * HID + n];
        g_WEs[idx] = acc;
    } else if (idx < 2400) {
        int r = (idx - 1200) / HID, n = idx % HID;
        float acc = 0.f;
        for (int k = 0; k < 20; ++k) acc += width_emb[r * 20 + k] * pW1[(1536 + k) * HID + n];
        g_WEt[idx - 1200] = acc;
    } else if (idx < 3600) {
        int r = (idx - 2400) / HID, n = idx % HID;
        float acc = 0.f;
        for (int k = 0; k < 20; ++k) acc += width_emb[r * 20 + k] * pW1[(3092 + k) * HID + n];
        g_WEo[idx - 2400] = acc;
    } else if (idx < 5100) {
        int r = (idx - 3600) / HID, n = idx % HID;
        float acc = pb1[n];
        for (int k = 0; k < 128; ++k) acc += dist_emb[r * 128 + k] * pW1[(3112 + k) * HID + n];
        g_Dtab[idx - 3600] = acc;
    }
}

// ---------------- proj GEMM: slabs [slab0, slab0+gridDim.y) ----------------
__global__ void __launch_bounds__(256) proj_gemm(
        const float* __restrict__ A,
        const float* __restrict__ sW1, const float* __restrict__ pW1, int slab0) {
    int tx = threadIdx.x, ty = threadIdx.y, tid = ty * 32 + tx;
    __shared__ __align__(16) float As[2][BMP][20];
    __shared__ __align__(16) float Ws[2][16][152];
    int m0 = blockIdx.x * BMP;
    int slab = slab0 + blockIdx.y;
    const float* src;
    switch (slab) {
        case 0: src = sW1; break;
        case 1: src = sW1 + 768 * HID; break;
        case 2: src = pW1; break;
        case 3: src = pW1 + 768 * HID; break;
        case 4: src = pW1 + 1556 * HID; break;
        default: src = pW1 + 2324 * HID; break;
    }
    const float2 z2 = make_float2(0.f, 0.f);
    float2 acc[4][3];
#pragma unroll
    for (int r = 0; r < 4; ++r)
#pragma unroll
        for (int t = 0; t < 3; ++t) acc[r][t] = z2;

    {
        int idx = tid;
#pragma unroll
        for (int i = 0; i < 2; ++i, idx += 256)
            As[0][idx >> 4][idx & 15] = A[(size_t)(m0 + (idx >> 4)) * HH + (idx & 15)];
        idx = tid;
#pragma unroll
        for (int i = 0; i < 10; ++i, idx += 256)
            if (idx < 2432) {
                int kk = idx / 152, c = idx % 152;
                Ws[0][kk][c] = (c < 150) ? src[(size_t)kk * HID + c] : 0.f;
            }
    }
    __syncthreads();

    const int NT = HH / 16;
    for (int t = 0; t < NT; ++t) {
        int buf = t & 1;
        float ar[2]; float wr[10];
        bool hasNext = (t + 1) < NT;
        if (hasNext) {
            int k0 = (t + 1) * 16;
            int idx = tid;
#pragma unroll
            for (int i = 0; i < 2; ++i, idx += 256)
                ar[i] = A[(size_t)(m0 + (idx >> 4)) * HH + k0 + (idx & 15)];
            idx = tid;
#pragma unroll
            for (int i = 0; i < 10; ++i, idx += 256)
                if (idx < 2432) {
                    int kk = idx / 152, c = idx % 152;
                    wr[i] = (c < 150) ? src[(size_t)(k0 + kk) * HID + c] : 0.f;
                }
        }
#pragma unroll
        for (int kkg = 0; kkg < 4; ++kkg) {
            float4 a4[4];
#pragma unroll
            for (int r = 0; r < 4; ++r)
                a4[r] = *reinterpret_cast<const float4*>(&As[buf][ty + 8 * r][kkg * 4]);
#pragma unroll
            for (int kki = 0; kki < 4; ++kki) {
                int kk = kkg * 4 + kki;
                const float2* wp = reinterpret_cast<const float2*>(&Ws[buf][kk][0]);
                float2 w0 = wp[tx], w1 = wp[tx + 32];
                float2 w2 = (tx < 11) ? wp[tx + 64] : z2;
#pragma unroll
                for (int r = 0; r < 4; ++r) {
                    float av = f4c(a4[r], kki);
                    float2 ad = make_float2(av, av);
                    acc[r][0] = ffma2(ad, w0, acc[r][0]);
                    acc[r][1] = ffma2(ad, w1, acc[r][1]);
                    acc[r][2] = ffma2(ad, w2, acc[r][2]);
                }
            }
        }
        if (hasNext) {
            int nb = buf ^ 1;
            int idx = tid;
#pragma unroll
            for (int i = 0; i < 2; ++i, idx += 256)
                As[nb][idx >> 4][idx & 15] = ar[i];
            idx = tid;
#pragma unroll
            for (int i = 0; i < 10; ++i, idx += 256)
                if (idx < 2432) Ws[nb][idx / 152][idx % 152] = wr[i];
        }
        __syncthreads();
    }
#pragma unroll
    for (int r = 0; r < 4; ++r) {
        int gm = m0 + ty + 8 * r;
        float2* orow = reinterpret_cast<float2*>(g_XH + (size_t)gm * NCAT + slab * HID);
        orow[tx] = acc[r][0];
        orow[tx + 32] = acc[r][1];
        if (tx < 11) orow[tx + 64] = acc[r][2];
    }
}

// ---------------- span pipeline — W resident, warp-private A, zero block syncs ----------------
__global__ void __launch_bounds__(256, 2) span_fused(
        const float* __restrict__ sW2, const float* __restrict__ sb2,
        const float* __restrict__ sW3, const float* __restrict__ sb3,
        float* __restrict__ outF) {
    extern __shared__ __align__(16) float smem[];
    float* Wsm = smem;
    float* AsS = smem + WSM_FLOATS;
    __shared__ float b2s[152];
    __shared__ float W3s[456];
    int tx = threadIdx.x, ty = threadIdx.y, tid = ty * 32 + tx;
    const float2 z2 = make_float2(0.f, 0.f);

    for (int idx = tid; idx < WSM_FLOATS; idx += 256) {
        int k = idx / WPITCH, c = idx % WPITCH;
        Wsm[idx] = (k < HID && c < HID) ? sW2[(size_t)k * HID + c] : 0.f;
    }
    for (int c = tid; c < 150; c += 256) b2s[c] = sb2[c];
    for (int c = tid; c < 450; c += 256) W3s[c] = sW3[c];
    if (tid < 3) W3s[450 + tid] = sb3[tid];

    int m0 = blockIdx.x * BMF;
    int kkl = tx & 15;
    int rbase = tx >> 4;
    int rowS_[4], rowE_[4], wOff_[4];
#pragma unroll
    for (int i = 0; i < 4; ++i) {
        int r = rbase + 2 * i;
        int gm = m0 + ty + 8 * r;
        if (gm < NSPANS_TOT) {
            int b = gm / NS, ii = gm % NS, s, e, w;
            span_decode(ii, s, e, w);
            rowS_[i] = (b * SS + s) * NCAT;
            rowE_[i] = (b * SS + e) * NCAT + 150;
            wOff_[i] = w * HID;
        } else rowS_[i] = -1;
    }
    __syncthreads();

    float* myAs = AsS + ty * 128;
    float h[4];
#pragma unroll
    for (int i = 0; i < 4; ++i) {
        h[i] = (rowS_[i] >= 0)
            ? fmaxf(g_XH[rowS_[i] + kkl] + g_XH[rowE_[i] + kkl] + g_WEs[wOff_[i] + kkl], 0.f) : 0.f;
        myAs[(rbase + 2 * i) * 16 + kkl] = h[i];
    }
    __syncwarp();

    float2 acc[8][3];
#pragma unroll
    for (int r = 0; r < 8; ++r)
#pragma unroll
        for (int t = 0; t < 3; ++t) acc[r][t] = z2;

    for (int t = 0; t < 10; ++t) {
        int buf = t & 1;
        bool hasNext = (t + 1) < 10;
        if (hasNext) {
            int gk = (t + 1) * 16 + kkl;
#pragma unroll
            for (int i = 0; i < 4; ++i)
                h[i] = (rowS_[i] >= 0 && gk < HID)
                    ? fmaxf(g_XH[rowS_[i] + gk] + g_XH[rowE_[i] + gk] + g_WEs[wOff_[i] + gk], 0.f) : 0.f;
        }
#pragma unroll
        for (int kkg = 0; kkg < 4; ++kkg) {
            float4 a4[8];
#pragma unroll
            for (int r = 0; r < 8; ++r)
                a4[r] = *reinterpret_cast<const float4*>(&AsS[buf * 1024 + ty * 128 + r * 16 + kkg * 4]);
#pragma unroll
            for (int kki = 0; kki < 4; ++kki) {
                int kk = kkg * 4 + kki;
                const float2* wp = reinterpret_cast<const float2*>(&Wsm[(t * 16 + kk) * WPITCH]);
                float2 w0 = wp[tx], w1 = wp[tx + 32];
                float2 w2 = (tx < 11) ? wp[tx + 64] : z2;
#pragma unroll
                for (int r = 0; r < 8; ++r) {
                    float av = f4c(a4[r], kki);
                    float2 ad = make_float2(av, av);
                    acc[r][0] = ffma2(ad, w0, acc[r][0]);
                    acc[r][1] = ffma2(ad, w1, acc[r][1]);
                    acc[r][2] = ffma2(ad, w2, acc[r][2]);
                }
            }
        }
        if (hasNext) {
            int nb = buf ^ 1;
#pragma unroll
            for (int i = 0; i < 4; ++i)
                AsS[nb * 1024 + ty * 128 + (rbase + 2 * i) * 16 + kkl] = h[i];
            __syncwarp();
        }
    }

#pragma unroll
    for (int rr = 0; rr < 8; ++rr) {
        int gm = m0 + ty + 8 * rr;
        float p0 = 0.f, p1 = 0.f, p2 = 0.f;
#pragma unroll
        for (int t = 0; t < 3; ++t) {
            int c0 = 2 * tx + 64 * t, c1 = c0 + 1;
            if (c0 < 150) {
                float v = fmaxf(acc[rr][t].x + b2s[c0], 0.f);
                p0 += v * W3s[c0 * 3 + 0]; p1 += v * W3s[c0 * 3 + 1]; p2 += v * W3s[c0 * 3 + 2];
            }
            if (c1 < 150) {
                float v = fmaxf(acc[rr][t].y + b2s[c1], 0.f);
                p0 += v * W3s[c1 * 3 + 0]; p1 += v * W3s[c1 * 3 + 1]; p2 += v * W3s[c1 * 3 + 2];
            }
        }
#pragma unroll
        for (int off = 16; off; off >>= 1) {
            p0 += __shfl_xor_sync(0xffffffffu, p0, off);
            p1 += __shfl_xor_sync(0xffffffffu, p1, off);
            p2 += __shfl_xor_sync(0xffffffffu, p2, off);
        }
        if (tx == 0 && gm < NSPANS_TOT) {
            float a0 = p0 + W3s[450], a1 = p1 + W3s[451], a2 = p2 + W3s[452];
            float m = fmaxf(a0, fmaxf(a1, a2));
            float e0 = expf(a0 - m), e1 = expf(a1 - m), e2 = expf(a2 - m);
            float inv = 1.f / (e0 + e1 + e2);
            float* o = outF + OUT_SPANS + (size_t)gm * 3;
            o[0] = e0 * inv; o[1] = e1 * inv; o[2] = e2 * inv;
            int b = gm / NS, i = gm % NS;
            g_probA[b * 1024 + i] = e1 * inv;
            g_probO[b * 1024 + i] = e2 * inv;
        }
    }
}

// ---------------- top-64 (hybrid shuffle bitonic) + pair-table gather ----------------
__global__ void topk_pair_kernel(float* __restrict__ outF) {
    __shared__ unsigned long long sk[1024];
    __shared__ int sS[64], sE[64], sW[64];
    int bx = blockIdx.x;
    int b = bx >> 1, cls = bx & 1;
    const float* src = cls ? g_probO : g_probA;
    int i = threadIdx.x;

    unsigned long long key;
    {
        float v = (i < NS) ? src[b * 1024 + i] : 0.f;
        unsigned vb = (i < NS) ? __float_as_uint(v) : 0u;
        key = ((unsigned long long)vb << 32) | (unsigned)(~i);
    }

    for (int k = 2; k <= 1024; k <<= 1) {
        bool up = ((i & k) == 0);
        for (int j = k >> 1; j > 0; j >>= 1) {
            unsigned long long o;
            if (j < 32) {
                o = __shfl_xor_sync(0xffffffffu, key, j);
            } else {
                sk[i] = key;
                __syncthreads();
                o = sk[i ^ j];
                __syncthreads();
            }
            bool iLower = ((i & j) == 0);
            bool takeMax = (iLower == up);
            key = takeMax ? (key > o ? key : o) : (key < o ? key : o);
        }
    }

    if (i < NZ) {
        int idx = ~((unsigned)key);
        int s, e, w; span_decode(idx, s, e, w);
        sS[i] = s; sE[i] = e; sW[i] = w;
        int bi = b * NZ + i;
        if (cls == 0) {
            g_tS[bi] = s; g_tE[bi] = e;
            outF[OUT_TIDX + bi] = (float)idx;
        } else {
            g_oS[bi] = s; g_oE[bi] = e;
            outF[OUT_OIDX + bi] = (float)idx;
        }
    }
    __syncthreads();

    const float* tab = cls ? g_WEo : g_WEt;
    float* dst = cls ? g_O : g_T;
    int off1 = cls ? 600 : 300, off2 = cls ? 750 : 450;
    for (int e2 = i; e2 < NZ * HID; e2 += 1024) {
        int r = e2 / HID, c = e2 % HID;
        const float* row_s = g_XH + (size_t)(b * SS + sS[r]) * NCAT;
        const float* row_e = g_XH + (size_t)(b * SS + sE[r]) * NCAT;
        dst[(size_t)(b * NZ + r) * HID + c] = row_s[off1 + c] + row_e[off2 + c] + tab[sW[r] * HID + c];
    }
}

// ---------------- pair pipeline — W resident, warp-private A, zero block syncs ----------------
__global__ void __launch_bounds__(256, 2) pair_fused(
        const float* __restrict__ pW2, const float* __restrict__ pb2,
        const float* __restrict__ pW3, const float* __restrict__ pb3,
        float* __restrict__ outF) {
    extern __shared__ __align__(16) float smem[];
    float* Wsm = smem;
    float* AsS = smem + WSM_FLOATS;
    __shared__ float b2s[152];
    __shared__ float W3s[608];
    int tx = threadIdx.x, ty = threadIdx.y, tid = ty * 32 + tx;
    const float2 z2 = make_float2(0.f, 0.f);

    for (int idx = tid; idx < WSM_FLOATS; idx += 256) {
        int k = idx / WPITCH, c = idx % WPITCH;
        Wsm[idx] = (k < HID && c < HID) ? pW2[(size_t)k * HID + c] : 0.f;
    }
    for (int c = tid; c < 150; c += 256) b2s[c] = pb2[c];
    for (int c = tid; c < 600; c += 256) W3s[c] = pW3[c];
    if (tid < 4) W3s[600 + tid] = pb3[tid];
    __syncthreads();

    int kkl = tx & 15;
    int rbase = tx >> 4;
    float* myAsBase = AsS + ty * 128;

    for (int tile = blockIdx.x; tile < NTILES_PAIR; tile += gridDim.x) {
        int p0 = tile * BMF;
        int b = tile >> 6;
        int i = tile & 63;
        int bi = b * NZ + i;
        int tSv = g_tS[bi], tEv = g_tE[bi];
        const float* Trow = g_T + (size_t)bi * HID;

        int oB_[4], dO_[4];
#pragma unroll
        for (int i2 = 0; i2 < 4; ++i2) {
            int r = rbase + 2 * i2;
            int bj = b * NZ + ty + 8 * r;
            oB_[i2] = bj * HID;
            int dist = min(abs(tEv - g_oS[bj]), abs(tSv - g_oE[bj]));
            int bucket = dist >= 64 ? 9 : dist >= 32 ? 8 : dist >= 16 ? 7 : dist >= 8 ? 6 : dist >= 5 ? 5 : dist;
            dO_[i2] = bucket * HID;
        }

        float h[4];
        {
            float tv = Trow[kkl];
#pragma unroll
            for (int i2 = 0; i2 < 4; ++i2) {
                h[i2] = fmaxf(tv + g_O[oB_[i2] + kkl] + g_Dtab[dO_[i2] + kkl], 0.f);
                myAsBase[(rbase + 2 * i2) * 16 + kkl] = h[i2];
            }
        }
        __syncwarp();

        float2 acc[8][3];
#pragma unroll
        for (int r = 0; r < 8; ++r)
#pragma unroll
            for (int t = 0; t < 3; ++t) acc[r][t] = z2;

        for (int t = 0; t < 10; ++t) {
            int buf = t & 1;
            bool hasNext = (t + 1) < 10;
            if (hasNext) {
                int gk = (t + 1) * 16 + kkl;
                float tv = (gk < HID) ? Trow[gk] : 0.f;
#pragma unroll
                for (int i2 = 0; i2 < 4; ++i2)
                    h[i2] = (gk < HID)
                        ? fmaxf(tv + g_O[oB_[i2] + gk] + g_Dtab[dO_[i2] + gk], 0.f) : 0.f;
            }
#pragma unroll
            for (int kkg = 0; kkg < 4; ++kkg) {
                float4 a4[8];
#pragma unroll
                for (int r = 0; r < 8; ++r)
                    a4[r] = *reinterpret_cast<const float4*>(&AsS[buf * 1024 + ty * 128 + r * 16 + kkg * 4]);
#pragma unroll
                for (int kki = 0; kki < 4; ++kki) {
                    int kk = kkg * 4 + kki;
                    const float2* wp = reinterpret_cast<const float2*>(&Wsm[(t * 16 + kk) * WPITCH]);
                    float2 w0 = wp[tx], w1 = wp[tx + 32];
                    float2 w2 = (tx < 11) ? wp[tx + 64] : z2;
#pragma unroll
                    for (int r = 0; r < 8; ++r) {
                        float av = f4c(a4[r], kki);
                        float2 ad = make_float2(av, av);
                        acc[r][0] = ffma2(ad, w0, acc[r][0]);
                        acc[r][1] = ffma2(ad, w1, acc[r][1]);
                        acc[r][2] = ffma2(ad, w2, acc[r][2]);
                    }
                }
            }
            if (hasNext) {
                int nb = buf ^ 1;
#pragma unroll
                for (int i2 = 0; i2 < 4; ++i2)
                    AsS[nb * 1024 + ty * 128 + (rbase + 2 * i2) * 16 + kkl] = h[i2];
                __syncwarp();
            }
        }

#pragma unroll
        for (int rr = 0; rr < 8; ++rr) {
            int gm = p0 + ty + 8 * rr;
            float q0 = 0.f, q1 = 0.f, q2 = 0.f, q3 = 0.f;
#pragma unroll
            for (int t = 0; t < 3; ++t) {
                int c0 = 2 * tx + 64 * t, c1 = c0 + 1;
                if (c0 < 150) {
                    float v = fmaxf(acc[rr][t].x + b2s[c0], 0.f);
                    q0 += v * W3s[c0 * 4 + 0]; q1 += v * W3s[c0 * 4 + 1];
                    q2 += v * W3s[c0 * 4 + 2]; q3 += v * W3s[c0 * 4 + 3];
                }
                if (c1 < 150) {
                    float v = fmaxf(acc[rr][t].y + b2s[c1], 0.f);
                    q0 += v * W3s[c1 * 4 + 0]; q1 += v * W3s[c1 * 4 + 1];
                    q2 += v * W3s[c1 * 4 + 2]; q3 += v * W3s[c1 * 4 + 3];
                }
            }
            q0 += __shfl_xor_sync(0xffffffffu, q0, 16);
            q1 += __shfl_xor_sync(0xffffffffu, q1, 16);
            q2 += __shfl_xor_sync(0xffffffffu, q2, 16);
            q3 += __shfl_xor_sync(0xffffffffu, q3, 16);
            float u = (tx & 16) ? q2 : q0;
            float v = (tx & 16) ? q3 : q1;
            u += __shfl_xor_sync(0xffffffffu, u, 8);
            v += __shfl_xor_sync(0xffffffffu, v, 8);
            float s = (tx & 8) ? v : u;
            s += __shfl_xor_sync(0xffffffffu, s, 4);
            s += __shfl_xor_sync(0xffffffffu, s, 2);
            s += __shfl_xor_sync(0xffffffffu, s, 1);
            float a0 = __shfl_sync(0xffffffffu, s, 0);
            float a1 = __shfl_sync(0xffffffffu, s, 8);
            float a2 = __shfl_sync(0xffffffffu, s, 16);
            float a3 = __shfl_sync(0xffffffffu, s, 24);
            if (tx == 0) {
                a0 += W3s[600]; a1 += W3s[601]; a2 += W3s[602]; a3 += W3s[603];
                float m = fmaxf(fmaxf(a0, a1), fmaxf(a2, a3));
                float e0 = expf(a0 - m), e1 = expf(a1 - m), e2 = expf(a2 - m), e3 = expf(a3 - m);
                float inv = 1.f / (e0 + e1 + e2 + e3);
                float4 ov = make_float4(e0 * inv, e1 * inv, e2 * inv, e3 * inv);
                *reinterpret_cast<float4*>(outF + OUT_CAND + (size_t)gm * 4) = ov;
            }
        }
    }
}

// ---------------- launch ----------------
extern "C" void kernel_launch(void* const* d_in, const int* in_sizes, int n_in,
                              void* d_out, int out_size) {
    const float* x        = (const float*)d_in[0];
    const float* width_e  = (const float*)d_in[1];
    const float* sW1      = (const float*)d_in[2];
    const float* sb1      = (const float*)d_in[3];
    const float* sW2      = (const float*)d_in[4];
    const float* sb2      = (const float*)d_in[5];
    const float* sW3      = (const float*)d_in[6];
    const float* sb3      = (const float*)d_in[7];
    const float* dist_e   = (const float*)d_in[8];
    const float* pW1      = (const float*)d_in[9];
    const float* pb1      = (const float*)d_in[10];
    const float* pW2      = (const float*)d_in[11];
    const float* pb2      = (const float*)d_in[12];
    const float* pW3      = (const float*)d_in[13];
    const float* pb3      = (const float*)d_in[14];
    float* outF = (float*)d_out;

    cudaFuncSetAttribute(span_fused, cudaFuncAttributeMaxDynamicSharedMemorySize, DYN_BYTES);
    cudaFuncSetAttribute(pair_fused, cudaFuncAttributeMaxDynamicSharedMemorySize, DYN_BYTES);

    dim3 blk(32, 8);

    // fork: side stream computes pair-side projection slabs (2..5) while the
    // default stream runs tables -> projA(0,1) -> span. Join before topk.
    cudaStream_t s1;
    cudaStreamCreateWithFlags(&s1, cudaStreamNonBlocking);
    cudaEvent_t e0, e1;
    cudaEventCreateWithFlags(&e0, cudaEventDisableTiming);
    cudaEventCreateWithFlags(&e1, cudaEventDisableTiming);

    cudaEventRecord(e0, 0);
    cudaStreamWaitEvent(s1, e0, 0);
    proj_gemm<<<dim3(BB * SS / BMP, 4), blk, 0, s1>>>(x, sW1, pW1, 2);   // slabs 2-5
    cudaEventRecord(e1, s1);

    tables_kernel<<<20, 256>>>(width_e, sW1, sb1, dist_e, pW1, pb1);
    proj_gemm<<<dim3(BB * SS / BMP, 2), blk>>>(x, sW1, pW1, 0);          // slabs 0,1
    span_fused<<<NTILES_SPAN, blk, DYN_BYTES>>>(sW2, sb2, sW3, sb3, outF);

    cudaStreamWaitEvent(0, e1, 0);
    topk_pair_kernel<<<BB * 2, 1024>>>(outF);
    pair_fused<<<256, blk, DYN_BYTES>>>(pW2, pb2, pW3, pb3, outF);
    // Intentionally no stream/event destroy: kernel_launch is invoked only for
    // the correctness run and the single capture call; destroying a stream that
    // participates in an active capture is illegal. Host-side handles only.
}

// round 12
// speedup vs baseline: 1.1250x; 1.1250x over previous
#include <cuda_runtime.h>
#include <math.h>
#include <float.h>

// ---------------- problem constants ----------------
#define BB 8
#define SS 128
#define HH 768
#define NS 996
#define HID 150
#define NZ 64
#define NPAIR (NZ*NZ)
#define NSPANS_TOT (BB*NS)      // 7968
#define NPAIRS_TOT (BB*NPAIR)   // 32768
#define NCAT 900
#define BMP 64                  // proj tile rows (r=8)
#define BMF 64                  // fused-GEMM tile rows (8 per warp)
#define WPITCH 152
#define WROWS 160
#define WSM_FLOATS (WROWS*WPITCH)          // 24320
#define ASM_FLOATS (2*8*8*16)              // 2048
#define DYN_BYTES ((WSM_FLOATS + ASM_FLOATS)*4)   // 105472

#define NTILES_SPAN ((NSPANS_TOT + BMF - 1)/BMF)  // 125
#define NTILES_PAIR (NPAIRS_TOT/BMF)              // 512

// output regions (floats)
#define OUT_SPANS 0
#define OUT_CAND  (BB*NS*3)                 // 23904
#define OUT_TIDX  (OUT_CAND + BB*NPAIR*4)   // 154976
#define OUT_OIDX  (OUT_TIDX + BB*NZ)        // 155488

// ---------------- scratch ----------------
__device__ float g_XH[BB * SS * NCAT];
__device__ float g_WEs[8 * HID];
__device__ float g_WEt[8 * HID];
__device__ float g_WEo[8 * HID];
__device__ float g_Dtab[10 * HID];
__device__ float g_probA[BB * 1024];
__device__ float g_probO[BB * 1024];
__device__ int   g_tS[BB * NZ], g_tE[BB * NZ], g_oS[BB * NZ], g_oE[BB * NZ];
__device__ float g_T[BB * NZ * HID];
__device__ float g_O[BB * NZ * HID];

// ---------------- packed fp32x2 FMA (Blackwell) ----------------
union F2U { float2 f; unsigned long long u; };
static __device__ __forceinline__ float2 ffma2(float2 a, float2 b, float2 c) {
    F2U A, B, C, D; A.f = a; B.f = b; C.f = c;
    asm("fma.rn.f32x2 %0, %1, %2, %3;" : "=l"(D.u) : "l"(A.u), "l"(B.u), "l"(C.u));
    return D.f;
}
static __device__ __forceinline__ float f4c(const float4& v, int k) {
    return k == 0 ? v.x : k == 1 ? v.y : k == 2 ? v.z : v.w;
}

__device__ __forceinline__ void span_decode(int i, int& s, int& e, int& w) {
    int off = 0;
#pragma unroll
    for (int wi = 1; wi <= 8; ++wi) {
        int cnt = SS - wi + 1;
        if (i < off + cnt) { s = i - off; e = s + wi - 1; w = wi - 1; return; }
        off += cnt;
    }
    s = 0; e = 0; w = 0;
}

// ---------------- resident-W staging helper (float2 + pad) ----------------
static __device__ __forceinline__ void stage_W(float* Wsm, const float* __restrict__ Wsrc, int tid) {
    const float2* wg = reinterpret_cast<const float2*>(Wsrc);
    for (int idx = tid; idx < 11250; idx += 256) {           // 150 rows * 75 float2
        int k = idx / 75, j = idx % 75;
        *reinterpret_cast<float2*>(&Wsm[k * WPITCH + 2 * j]) = wg[idx];
    }
    for (int idx = tid; idx < 1820; idx += 256) {            // pad: cols 150-151 + rows 150-159
        int k, c;
        if (idx < 300) { k = idx >> 1; c = 150 + (idx & 1); }
        else { k = 150 + (idx - 300) / WPITCH; c = (idx - 300) % WPITCH; }
        Wsm[k * WPITCH + c] = 0.f;
    }
}

// ---------------- tiny tables ----------------
__global__ void tables_kernel(const float* __restrict__ width_emb,
                              const float* __restrict__ sW1, const float* __restrict__ sb1,
                              const float* __restrict__ dist_emb,
                              const float* __restrict__ pW1, const float* __restrict__ pb1) {
    int idx = blockIdx.x * 256 + threadIdx.x;
    if (idx < 1200) {
        int r = idx / HID, n = idx % HID;
        float acc = sb1[n];
        for (int k = 0; k < 20; ++k) acc += width_emb[r * 20 + k] * sW1[(1536 + k) * HID + n];
        g_WEs[idx] = acc;
    } else if (idx < 2400) {
        int r = (idx - 1200) / HID, n = idx % HID;
        float acc = 0.f;
        for (int k = 0; k < 20; ++k) acc += width_emb[r * 20 + k] * pW1[(1536 + k) * HID + n];
        g_WEt[idx - 1200] = acc;
    } else if (idx < 3600) {
        int r = (idx - 2400) / HID, n = idx % HID;
        float acc = 0.f;
        for (int k = 0; k < 20; ++k) acc += width_emb[r * 20 + k] * pW1[(3092 + k) * HID + n];
        g_WEo[idx - 2400] = acc;
    } else if (idx < 5100) {
        int r = (idx - 3600) / HID, n = idx % HID;
        float acc = pb1[n];
        for (int k = 0; k < 128; ++k) acc += dist_emb[r * 128 + k] * pW1[(3112 + k) * HID + n];
        g_Dtab[idx - 3600] = acc;
    }
}

// ---------------- proj GEMM: BMP=64, r=8, double-buffered ----------------
__global__ void __launch_bounds__(256) proj_gemm(
        const float* __restrict__ A,
        const float* __restrict__ sW1, const float* __restrict__ pW1) {
    int tx = threadIdx.x, ty = threadIdx.y, tid = ty * 32 + tx;
    __shared__ __align__(16) float As[2][BMP][20];
    __shared__ __align__(16) float Ws[2][16][152];
    int m0 = blockIdx.x * BMP;
    int slab = blockIdx.y;
    const float* src;
    switch (slab) {
        case 0: src = sW1; break;
        case 1: src = sW1 + 768 * HID; break;
        case 2: src = pW1; break;
        case 3: src = pW1 + 768 * HID; break;
        case 4: src = pW1 + 1556 * HID; break;
        default: src = pW1 + 2324 * HID; break;
    }
    const float2 z2 = make_float2(0.f, 0.f);
    float2 acc[8][3];
#pragma unroll
    for (int r = 0; r < 8; ++r)
#pragma unroll
        for (int t = 0; t < 3; ++t) acc[r][t] = z2;

    {
        int idx = tid;                        // A: 64*16 = 1024 elems, 4/thread
#pragma unroll
        for (int i = 0; i < 4; ++i, idx += 256)
            As[0][idx >> 4][idx & 15] = A[(size_t)(m0 + (idx >> 4)) * HH + (idx & 15)];
        idx = tid;
#pragma unroll
        for (int i = 0; i < 10; ++i, idx += 256)
            if (idx < 2432) {
                int kk = idx / 152, c = idx % 152;
                Ws[0][kk][c] = (c < 150) ? src[(size_t)kk * HID + c] : 0.f;
            }
    }
    __syncthreads();

    const int NT = HH / 16;
    for (int t = 0; t < NT; ++t) {
        int buf = t & 1;
        float ar[4]; float wr[10];
        bool hasNext = (t + 1) < NT;
        if (hasNext) {
            int k0 = (t + 1) * 16;
            int idx = tid;
#pragma unroll
            for (int i = 0; i < 4; ++i, idx += 256)
                ar[i] = A[(size_t)(m0 + (idx >> 4)) * HH + k0 + (idx & 15)];
            idx = tid;
#pragma unroll
            for (int i = 0; i < 10; ++i, idx += 256)
                if (idx < 2432) {
                    int kk = idx / 152, c = idx % 152;
                    wr[i] = (c < 150) ? src[(size_t)(k0 + kk) * HID + c] : 0.f;
                }
        }
#pragma unroll
        for (int kkg = 0; kkg < 4; ++kkg) {
            float4 a4[8];
#pragma unroll
            for (int r = 0; r < 8; ++r)
                a4[r] = *reinterpret_cast<const float4*>(&As[buf][ty + 8 * r][kkg * 4]);
#pragma unroll
            for (int kki = 0; kki < 4; ++kki) {
                int kk = kkg * 4 + kki;
                const float2* wp = reinterpret_cast<const float2*>(&Ws[buf][kk][0]);
                float2 w0 = wp[tx], w1 = wp[tx + 32];
                float2 w2 = (tx < 11) ? wp[tx + 64] : z2;
#pragma unroll
                for (int r = 0; r < 8; ++r) {
                    float av = f4c(a4[r], kki);
                    float2 ad = make_float2(av, av);
                    acc[r][0] = ffma2(ad, w0, acc[r][0]);
                    acc[r][1] = ffma2(ad, w1, acc[r][1]);
                    acc[r][2] = ffma2(ad, w2, acc[r][2]);
                }
            }
        }
        if (hasNext) {
            int nb = buf ^ 1;
            int idx = tid;
#pragma unroll
            for (int i = 0; i < 4; ++i, idx += 256)
                As[nb][idx >> 4][idx & 15] = ar[i];
            idx = tid;
#pragma unroll
            for (int i = 0; i < 10; ++i, idx += 256)
                if (idx < 2432) Ws[nb][idx / 152][idx % 152] = wr[i];
        }
        __syncthreads();
    }
#pragma unroll
    for (int r = 0; r < 8; ++r) {
        int gm = m0 + ty + 8 * r;
        float2* orow = reinterpret_cast<float2*>(g_XH + (size_t)gm * NCAT + slab * HID);
        orow[tx] = acc[r][0];
        orow[tx + 32] = acc[r][1];
        if (tx < 11) orow[tx + 64] = acc[r][2];
    }
}

// ---------------- span pipeline — W resident, warp-private A, zero block syncs ----------------
__global__ void __launch_bounds__(256, 2) span_fused(
        const float* __restrict__ sW2, const float* __restrict__ sb2,
        const float* __restrict__ sW3, const float* __restrict__ sb3,
        float* __restrict__ outF) {
    extern __shared__ __align__(16) float smem[];
    float* Wsm = smem;
    float* AsS = smem + WSM_FLOATS;
    __shared__ float b2s[152];
    __shared__ float W3s[456];
    int tx = threadIdx.x, ty = threadIdx.y, tid = ty * 32 + tx;
    const float2 z2 = make_float2(0.f, 0.f);

    stage_W(Wsm, sW2, tid);
    for (int c = tid; c < 150; c += 256) b2s[c] = sb2[c];
    for (int c = tid; c < 450; c += 256) W3s[c] = sW3[c];
    if (tid < 3) W3s[450 + tid] = sb3[tid];

    int m0 = blockIdx.x * BMF;
    int kkl = tx & 15;
    int rbase = tx >> 4;
    int rowS_[4], rowE_[4], wOff_[4];
#pragma unroll
    for (int i = 0; i < 4; ++i) {
        int r = rbase + 2 * i;
        int gm = m0 + ty + 8 * r;
        if (gm < NSPANS_TOT) {
            int b = gm / NS, ii = gm % NS, s, e, w;
            span_decode(ii, s, e, w);
            rowS_[i] = (b * SS + s) * NCAT;
            rowE_[i] = (b * SS + e) * NCAT + 150;
            wOff_[i] = w * HID;
        } else rowS_[i] = -1;
    }
    __syncthreads();

    float* myAs = AsS + ty * 128;
    float h[4];
#pragma unroll
    for (int i = 0; i < 4; ++i) {
        h[i] = (rowS_[i] >= 0)
            ? fmaxf(g_XH[rowS_[i] + kkl] + g_XH[rowE_[i] + kkl] + g_WEs[wOff_[i] + kkl], 0.f) : 0.f;
        myAs[(rbase + 2 * i) * 16 + kkl] = h[i];
    }
    __syncwarp();

    float2 acc[8][3];
#pragma unroll
    for (int r = 0; r < 8; ++r)
#pragma unroll
        for (int t = 0; t < 3; ++t) acc[r][t] = z2;

    for (int t = 0; t < 10; ++t) {
        int buf = t & 1;
        bool hasNext = (t + 1) < 10;
        if (hasNext) {
            int gk = (t + 1) * 16 + kkl;
#pragma unroll
            for (int i = 0; i < 4; ++i)
                h[i] = (rowS_[i] >= 0 && gk < HID)
                    ? fmaxf(g_XH[rowS_[i] + gk] + g_XH[rowE_[i] + gk] + g_WEs[wOff_[i] + gk], 0.f) : 0.f;
        }
#pragma unroll
        for (int kkg = 0; kkg < 4; ++kkg) {
            float4 a4[8];
#pragma unroll
            for (int r = 0; r < 8; ++r)
                a4[r] = *reinterpret_cast<const float4*>(&AsS[buf * 1024 + ty * 128 + r * 16 + kkg * 4]);
#pragma unroll
            for (int kki = 0; kki < 4; ++kki) {
                int kk = kkg * 4 + kki;
                const float2* wp = reinterpret_cast<const float2*>(&Wsm[(t * 16 + kk) * WPITCH]);
                float2 w0 = wp[tx], w1 = wp[tx + 32];
                float2 w2 = (tx < 11) ? wp[tx + 64] : z2;
#pragma unroll
                for (int r = 0; r < 8; ++r) {
                    float av = f4c(a4[r], kki);
                    float2 ad = make_float2(av, av);
                    acc[r][0] = ffma2(ad, w0, acc[r][0]);
                    acc[r][1] = ffma2(ad, w1, acc[r][1]);
                    acc[r][2] = ffma2(ad, w2, acc[r][2]);
                }
            }
        }
        if (hasNext) {
            int nb = buf ^ 1;
#pragma unroll
            for (int i = 0; i < 4; ++i)
                AsS[nb * 1024 + ty * 128 + (rbase + 2 * i) * 16 + kkl] = h[i];
            __syncwarp();
        }
    }

#pragma unroll
    for (int rr = 0; rr < 8; ++rr) {
        int gm = m0 + ty + 8 * rr;
        float p0 = 0.f, p1 = 0.f, p2 = 0.f;
#pragma unroll
        for (int t = 0; t < 3; ++t) {
            int c0 = 2 * tx + 64 * t, c1 = c0 + 1;
            if (c0 < 150) {
                float v = fmaxf(acc[rr][t].x + b2s[c0], 0.f);
                p0 += v * W3s[c0 * 3 + 0]; p1 += v * W3s[c0 * 3 + 1]; p2 += v * W3s[c0 * 3 + 2];
            }
            if (c1 < 150) {
                float v = fmaxf(acc[rr][t].y + b2s[c1], 0.f);
                p0 += v * W3s[c1 * 3 + 0]; p1 += v * W3s[c1 * 3 + 1]; p2 += v * W3s[c1 * 3 + 2];
            }
        }
#pragma unroll
        for (int off = 16; off; off >>= 1) {
            p0 += __shfl_xor_sync(0xffffffffu, p0, off);
            p1 += __shfl_xor_sync(0xffffffffu, p1, off);
            p2 += __shfl_xor_sync(0xffffffffu, p2, off);
        }
        if (tx == 0 && gm < NSPANS_TOT) {
            float a0 = p0 + W3s[450], a1 = p1 + W3s[451], a2 = p2 + W3s[452];
            float m = fmaxf(a0, fmaxf(a1, a2));
            float e0 = expf(a0 - m), e1 = expf(a1 - m), e2 = expf(a2 - m);
            float inv = 1.f / (e0 + e1 + e2);
            float* o = outF + OUT_SPANS + (size_t)gm * 3;
            o[0] = e0 * inv; o[1] = e1 * inv; o[2] = e2 * inv;
            int b = gm / NS, i = gm % NS;
            g_probA[b * 1024 + i] = e1 * inv;
            g_probO[b * 1024 + i] = e2 * inv;
        }
    }
}

// ---------------- top-64 (hybrid shuffle bitonic) + pair-table gather ----------------
__global__ void topk_pair_kernel(float* __restrict__ outF) {
    __shared__ unsigned long long sk[1024];
    __shared__ int sS[64], sE[64], sW[64];
    int bx = blockIdx.x;
    int b = bx >> 1, cls = bx & 1;
    const float* src = cls ? g_probO : g_probA;
    int i = threadIdx.x;

    unsigned long long key;
    {
        float v = (i < NS) ? src[b * 1024 + i] : 0.f;
        unsigned vb = (i < NS) ? __float_as_uint(v) : 0u;
        key = ((unsigned long long)vb << 32) | (unsigned)(~i);
    }

    for (int k = 2; k <= 1024; k <<= 1) {
        bool up = ((i & k) == 0);
        for (int j = k >> 1; j > 0; j >>= 1) {
            unsigned long long o;
            if (j < 32) {
                o = __shfl_xor_sync(0xffffffffu, key, j);
            } else {
                sk[i] = key;
                __syncthreads();
                o = sk[i ^ j];
                __syncthreads();
            }
            bool iLower = ((i & j) == 0);
            bool takeMax = (iLower == up);
            key = takeMax ? (key > o ? key : o) : (key < o ? key : o);
        }
    }

    if (i < NZ) {
        int idx = ~((unsigned)key);
        int s, e, w; span_decode(idx, s, e, w);
        sS[i] = s; sE[i] = e; sW[i] = w;
        int bi = b * NZ + i;
        if (cls == 0) {
            g_tS[bi] = s; g_tE[bi] = e;
            outF[OUT_TIDX + bi] = (float)idx;
        } else {
            g_oS[bi] = s; g_oE[bi] = e;
            outF[OUT_OIDX + bi] = (float)idx;
        }
    }
    __syncthreads();

    const float* tab = cls ? g_WEo : g_WEt;
    float* dst = cls ? g_O : g_T;
    int off1 = cls ? 600 : 300, off2 = cls ? 750 : 450;
    for (int e2 = i; e2 < NZ * HID; e2 += 1024) {
        int r = e2 / HID, c = e2 % HID;
        const float* row_s = g_XH + (size_t)(b * SS + sS[r]) * NCAT;
        const float* row_e = g_XH + (size_t)(b * SS + sE[r]) * NCAT;
        dst[(size_t)(b * NZ + r) * HID + c] = row_s[off1 + c] + row_e[off2 + c] + tab[sW[r] * HID + c];
    }
}

// ---------------- pair pipeline — W resident, warp-private A, zero block syncs ----------------
__global__ void __launch_bounds__(256, 2) pair_fused(
        const float* __restrict__ pW2, const float* __restrict__ pb2,
        const float* __restrict__ pW3, const float* __restrict__ pb3,
        float* __restrict__ outF) {
    extern __shared__ __align__(16) float smem[];
    float* Wsm = smem;
    float* AsS = smem + WSM_FLOATS;
    __shared__ float b2s[152];
    __shared__ float W3s[608];
    int tx = threadIdx.x, ty = threadIdx.y, tid = ty * 32 + tx;
    const float2 z2 = make_float2(0.f, 0.f);

    stage_W(Wsm, pW2, tid);
    for (int c = tid; c < 150; c += 256) b2s[c] = pb2[c];
    for (int c = tid; c < 600; c += 256) W3s[c] = pW3[c];
    if (tid < 4) W3s[600 + tid] = pb3[tid];
    __syncthreads();

    int kkl = tx & 15;
    int rbase = tx >> 4;
    float* myAsBase = AsS + ty * 128;

    for (int tile = blockIdx.x; tile < NTILES_PAIR; tile += gridDim.x) {
        int p0 = tile * BMF;
        int b = tile >> 6;
        int i = tile & 63;
        int bi = b * NZ + i;
        int tSv = g_tS[bi], tEv = g_tE[bi];
        const float* Trow = g_T + (size_t)bi * HID;

        int oB_[4], dO_[4];
#pragma unroll
        for (int i2 = 0; i2 < 4; ++i2) {
            int r = rbase + 2 * i2;
            int bj = b * NZ + ty + 8 * r;
            oB_[i2] = bj * HID;
            int dist = min(abs(tEv - g_oS[bj]), abs(tSv - g_oE[bj]));
            int bucket = dist >= 64 ? 9 : dist >= 32 ? 8 : dist >= 16 ? 7 : dist >= 8 ? 6 : dist >= 5 ? 5 : dist;
            dO_[i2] = bucket * HID;
        }

        float h[4];
        {
            float tv = Trow[kkl];
#pragma unroll
            for (int i2 = 0; i2 < 4; ++i2) {
                h[i2] = fmaxf(tv + g_O[oB_[i2] + kkl] + g_Dtab[dO_[i2] + kkl], 0.f);
                myAsBase[(rbase + 2 * i2) * 16 + kkl] = h[i2];
            }
        }
        __syncwarp();

        float2 acc[8][3];
#pragma unroll
        for (int r = 0; r < 8; ++r)
#pragma unroll
            for (int t = 0; t < 3; ++t) acc[r][t] = z2;

        for (int t = 0; t < 10; ++t) {
            int buf = t & 1;
            bool hasNext = (t + 1) < 10;
            if (hasNext) {
                int gk = (t + 1) * 16 + kkl;
                float tv = (gk < HID) ? Trow[gk] : 0.f;
#pragma unroll
                for (int i2 = 0; i2 < 4; ++i2)
                    h[i2] = (gk < HID)
                        ? fmaxf(tv + g_O[oB_[i2] + gk] + g_Dtab[dO_[i2] + gk], 0.f) : 0.f;
            }
#pragma unroll
            for (int kkg = 0; kkg < 4; ++kkg) {
                float4 a4[8];
#pragma unroll
                for (int r = 0; r < 8; ++r)
                    a4[r] = *reinterpret_cast<const float4*>(&AsS[buf * 1024 + ty * 128 + r * 16 + kkg * 4]);
#pragma unroll
                for (int kki = 0; kki < 4; ++kki) {
                    int kk = kkg * 4 + kki;
                    const float2* wp = reinterpret_cast<const float2*>(&Wsm[(t * 16 + kk) * WPITCH]);
                    float2 w0 = wp[tx], w1 = wp[tx + 32];
                    float2 w2 = (tx < 11) ? wp[tx + 64] : z2;
#pragma unroll
                    for (int r = 0; r < 8; ++r) {
                        float av = f4c(a4[r], kki);
                        float2 ad = make_float2(av, av);
                        acc[r][0] = ffma2(ad, w0, acc[r][0]);
                        acc[r][1] = ffma2(ad, w1, acc[r][1]);
                        acc[r][2] = ffma2(ad, w2, acc[r][2]);
                    }
                }
            }
            if (hasNext) {
                int nb = buf ^ 1;
#pragma unroll
                for (int i2 = 0; i2 < 4; ++i2)
                    AsS[nb * 1024 + ty * 128 + (rbase + 2 * i2) * 16 + kkl] = h[i2];
                __syncwarp();
            }
        }

#pragma unroll
        for (int rr = 0; rr < 8; ++rr) {
            int gm = p0 + ty + 8 * rr;
            float q0 = 0.f, q1 = 0.f, q2 = 0.f, q3 = 0.f;
#pragma unroll
            for (int t = 0; t < 3; ++t) {
                int c0 = 2 * tx + 64 * t, c1 = c0 + 1;
                if (c0 < 150) {
                    float v = fmaxf(acc[rr][t].x + b2s[c0], 0.f);
                    q0 += v * W3s[c0 * 4 + 0]; q1 += v * W3s[c0 * 4 + 1];
                    q2 += v * W3s[c0 * 4 + 2]; q3 += v * W3s[c0 * 4 + 3];
                }
                if (c1 < 150) {
                    float v = fmaxf(acc[rr][t].y + b2s[c1], 0.f);
                    q0 += v * W3s[c1 * 4 + 0]; q1 += v * W3s[c1 * 4 + 1];
                    q2 += v * W3s[c1 * 4 + 2]; q3 += v * W3s[c1 * 4 + 3];
                }
            }
            q0 += __shfl_xor_sync(0xffffffffu, q0, 16);
            q1 += __shfl_xor_sync(0xffffffffu, q1, 16);
            q2 += __shfl_xor_sync(0xffffffffu, q2, 16);
            q3 += __shfl_xor_sync(0xffffffffu, q3, 16);
            float u = (tx & 16) ? q2 : q0;
            float v = (tx & 16) ? q3 : q1;
            u += __shfl_xor_sync(0xffffffffu, u, 8);
            v += __shfl_xor_sync(0xffffffffu, v, 8);
            float s = (tx & 8) ? v : u;
            s += __shfl_xor_sync(0xffffffffu, s, 4);
            s += __shfl_xor_sync(0xffffffffu, s, 2);
            s += __shfl_xor_sync(0xffffffffu, s, 1);
            float a0 = __shfl_sync(0xffffffffu, s, 0);
            float a1 = __shfl_sync(0xffffffffu, s, 8);
            float a2 = __shfl_sync(0xffffffffu, s, 16);
            float a3 = __shfl_sync(0xffffffffu, s, 24);
            if (tx == 0) {
                a0 += W3s[600]; a1 += W3s[601]; a2 += W3s[602]; a3 += W3s[603];
                float m = fmaxf(fmaxf(a0, a1), fmaxf(a2, a3));
                float e0 = expf(a0 - m), e1 = expf(a1 - m), e2 = expf(a2 - m), e3 = expf(a3 - m);
                float inv = 1.f / (e0 + e1 + e2 + e3);
                float4 ov = make_float4(e0 * inv, e1 * inv, e2 * inv, e3 * inv);
                *reinterpret_cast<float4*>(outF + OUT_CAND + (size_t)gm * 4) = ov;
            }
        }
    }
}

// ---------------- launch ----------------
extern "C" void kernel_launch(void* const* d_in, const int* in_sizes, int n_in,
                              void* d_out, int out_size) {
    const float* x        = (const float*)d_in[0];
    const float* width_e  = (const float*)d_in[1];
    const float* sW1      = (const float*)d_in[2];
    const float* sb1      = (const float*)d_in[3];
    const float* sW2      = (const float*)d_in[4];
    const float* sb2      = (const float*)d_in[5];
    const float* sW3      = (const float*)d_in[6];
    const float* sb3      = (const float*)d_in[7];
    const float* dist_e   = (const float*)d_in[8];
    const float* pW1      = (const float*)d_in[9];
    const float* pb1      = (const float*)d_in[10];
    const float* pW2      = (const float*)d_in[11];
    const float* pb2      = (const float*)d_in[12];
    const float* pW3      = (const float*)d_in[13];
    const float* pb3      = (const float*)d_in[14];
    float* outF = (float*)d_out;

    cudaFuncSetAttribute(span_fused, cudaFuncAttributeMaxDynamicSharedMemorySize, DYN_BYTES);
    cudaFuncSetAttribute(pair_fused, cudaFuncAttributeMaxDynamicSharedMemorySize, DYN_BYTES);

    dim3 blk(32, 8);

    tables_kernel<<<20, 256>>>(width_e, sW1, sb1, dist_e, pW1, pb1);
    proj_gemm<<<dim3(BB * SS / BMP, 6), blk>>>(x, sW1, pW1);
    span_fused<<<NTILES_SPAN, blk, DYN_BYTES>>>(sW2, sb2, sW3, sb3, outF);
    topk_pair_kernel<<<BB * 2, 1024>>>(outF);
    pair_fused<<<256, blk, DYN_BYTES>>>(pW2, pb2, pW3, pb3, outF);
}